// round 4
// baseline (speedup 1.0000x reference)
#include <cuda_runtime.h>
#include <math.h>

#define IMG_H   128
#define IMG_W   128
#define NB      4
#define IMG     (IMG_H * IMG_W)          // 16384
#define NPIX    (NB * IMG)               // 65536
#define NINT    1000
#define STRIPS  16
#define SROWS   8                        // output rows per strip
#define GBLK    (NB * STRIPS)            // 64 blocks (4 img x 16 strips)
#define THREADS 256
#define NWARP   (THREADS / 32)
#define ST      129                      // padded smem row stride
#define MAXR    16                       // 8 + 4 halo each side
#define FULLM   0xffffffffu

// Static device scratch (no allocations allowed)
__device__ float g_mn[GBLK], g_mx[GBLK], g_ws[GBLK];
__device__ int   g_cnt[GBLK];
__device__ unsigned g_bar1;              // grid barrier ticket (monotonic)
__device__ unsigned g_bar2;              // last-block ticket (monotonic)

__global__ void __launch_bounds__(THREADS, 1)
fused_loss(const float* __restrict__ pred, const float* __restrict__ tgt,
           float* __restrict__ out) {
    __shared__ float imgA[MAXR * ST];    // pred strip
    __shared__ float imgB[MAXR * ST];    // tgt strip
    __shared__ float hsA [MAXR * ST];    // horizontal sums, pred
    __shared__ float hsB [MAXR * ST];    // horizontal sums, tgt
    __shared__ float wmn[NWARP], wmx[NWARP], wws[NWARP];
    __shared__ int   wci[NWARP];
    __shared__ float bc_lo, bc_dx;
    __shared__ int   bc_last;

    const int tid  = threadIdx.x;
    const int lane = tid & 31;
    const int wid  = tid >> 5;
    const int b    = blockIdx.x;
    const int im   = b >> 4;
    const int strip = b & 15;

    const int y0 = strip * SROWS;
    const int lo = max(0, y0 - 4);
    const int hi = min(IMG_H, y0 + SROWS + 4);
    const int nrows = hi - lo;

    // ---- load both strips (float4), fuse wmse on strip-owned rows --------
    float wsum = 0.0f;
    {
        const float4* p4 = (const float4*)(pred + (im * IMG + lo * IMG_W));
        const float4* t4 = (const float4*)(tgt  + (im * IMG + lo * IMG_W));
        const int n4 = nrows * (IMG_W / 4);
        for (int i = tid; i < n4; i += THREADS) {
            float4 pv = p4[i];
            float4 tv = t4[i];
            int base = i * 4;
            int r = base >> 7, x = base & 127;
            float* pa = imgA + r * ST + x;
            float* pb = imgB + r * ST + x;
            pa[0] = pv.x; pa[1] = pv.y; pa[2] = pv.z; pa[3] = pv.w;
            pb[0] = tv.x; pb[1] = tv.y; pb[2] = tv.z; pb[3] = tv.w;
            const int gy = lo + r;
            if (gy >= y0 && gy < y0 + SROWS) {
                float pp[4] = {pv.x, pv.y, pv.z, pv.w};
                float tt[4] = {tv.x, tv.y, tv.z, tv.w};
                #pragma unroll
                for (int k = 0; k < 4; ++k) {
                    float t = tt[k];
                    float w = 1.0f;
                    if (t >= 0.5f)  w = 2.0f;
                    if (t >= 2.0f)  w = 5.0f;
                    if (t >= 5.0f)  w = 10.0f;
                    if (t >= 10.0f) w = 30.0f;
                    float d = pp[k] - t;
                    wsum += w * d * d;
                }
            }
        }
    }
    __syncthreads();

    // ---- horizontal sliding sums, BOTH tensors interleaved (ILP) ---------
    if (tid < nrows * 16) {
        const int r  = tid >> 4;
        const int x0 = (tid & 15) * 8;
        const float* rowA = imgA + r * ST;
        const float* rowB = imgB + r * ST;
        float* hrA = hsA + r * ST;
        float* hrB = hsB + r * ST;
        float sA = 0.0f, sB = 0.0f;
        #pragma unroll
        for (int dx = -4; dx <= 4; ++dx) {
            int xx = x0 + dx;
            if (xx >= 0 && xx < IMG_W) { sA += rowA[xx]; sB += rowB[xx]; }
        }
        #pragma unroll
        for (int k = 0; k < 8; ++k) {
            const int xc = x0 + k;
            hrA[xc] = sA; hrB[xc] = sB;
            if (xc + 5 < IMG_W) { sA += rowA[xc + 5]; sB += rowB[xc + 5]; }
            if (xc - 4 >= 0)    { sA -= rowA[xc - 4]; sB -= rowB[xc - 4]; }
        }
    }
    __syncthreads();

    // ---- vertical sliding sums + distance (regs), both tensors ----------
    const int x   = tid & 127;
    const int seg = tid >> 7;            // 0 or 1
    const int yb  = y0 + seg * 4;
    const int cx  = min(x + 4, IMG_W - 1) - max(x - 4, 0) + 1;

    float dA[4], dB[4];
    float mn = INFINITY, mx = -INFINITY;
    {
        float sA = 0.0f, sB = 0.0f;
        const int wlo = max(0, yb - 4), whi = min(IMG_H - 1, yb + 4);
        for (int yy = wlo; yy <= whi; ++yy) {
            sA += hsA[(yy - lo) * ST + x];
            sB += hsB[(yy - lo) * ST + x];
        }
        #pragma unroll
        for (int k = 0; k < 4; ++k) {
            const int y  = yb + k;
            const int cy = min(y + 4, IMG_H - 1) - max(y - 4, 0) + 1;
            const float inv = 1.0f / (float)(cx * cy);
            const float da = imgA[(y - lo) * ST + x] - sA * inv;
            const float db = imgB[(y - lo) * ST + x] - sB * inv;
            dA[k] = da; dB[k] = db;
            mn = fminf(mn, fminf(da, db));
            mx = fmaxf(mx, fmaxf(da, db));
            if (k < 3) {
                if (y + 5 < IMG_H) { sA += hsA[(y + 5 - lo) * ST + x];
                                     sB += hsB[(y + 5 - lo) * ST + x]; }
                if (y - 4 >= 0)    { sA -= hsA[(y - 4 - lo) * ST + x];
                                     sB -= hsB[(y - 4 - lo) * ST + x]; }
            }
        }
    }

    // NOTE: reference divides by exact count cx*cy; 1/(cx*cy) in fp32 differs
    // from x/ (cx*cy) by <=1ulp — use division to stay bit-faithful:
    // (recompute mean with division for exactness)
    // -- handled above via inv; acceptable: changes dist by ~1e-7 rel, far
    //    below the 1e-3 threshold and deterministic.

    // ---- warp-shuffle min/max reduction, publish per-block ---------------
    #pragma unroll
    for (int o = 16; o > 0; o >>= 1) {
        mn = fminf(mn, __shfl_xor_sync(FULLM, mn, o));
        mx = fmaxf(mx, __shfl_xor_sync(FULLM, mx, o));
    }
    if (lane == 0) { wmn[wid] = mn; wmx[wid] = mx; }
    __syncthreads();
    if (wid == 0) {
        float m1 = (lane < NWARP) ? wmn[lane] : INFINITY;
        float m2 = (lane < NWARP) ? wmx[lane] : -INFINITY;
        #pragma unroll
        for (int o = 4; o > 0; o >>= 1) {
            m1 = fminf(m1, __shfl_xor_sync(FULLM, m1, o));
            m2 = fmaxf(m2, __shfl_xor_sync(FULLM, m2, o));
        }
        if (lane == 0) { g_mn[b] = m1; g_mx[b] = m2; }
    }

    // ---- grid barrier (replay-safe monotonic ticket) ----------------------
    __syncthreads();
    if (tid == 0) {
        __threadfence();
        unsigned t   = atomicAdd(&g_bar1, 1u);
        unsigned tgt2 = (t / (unsigned)GBLK + 1u) * (unsigned)GBLK;
        while (*(volatile unsigned*)&g_bar1 < tgt2) { }
        __threadfence();
    }
    __syncthreads();

    // ---- fold global lo/dx with one warp ----------------------------------
    if (wid == 0) {
        float m1 = fminf(g_mn[lane], g_mn[lane + 32]);
        float m2 = fmaxf(g_mx[lane], g_mx[lane + 32]);
        #pragma unroll
        for (int o = 16; o > 0; o >>= 1) {
            m1 = fminf(m1, __shfl_xor_sync(FULLM, m1, o));
            m2 = fmaxf(m2, __shfl_xor_sync(FULLM, m2, o));
        }
        if (lane == 0) { bc_lo = m1; bc_dx = (m2 - m1) / (float)(NINT - 1); }
    }
    __syncthreads();
    const float flo = bc_lo;
    const float fdx = bc_dx;

    // ---- CRPS counts from register-resident dist pairs (exact ints) ------
    int cnt = 0;
    #pragma unroll
    for (int k = 0; k < 4; ++k) {
        const float a = fminf(dA[k], dB[k]);
        const float c = fmaxf(dA[k], dB[k]);
        int ja = (int)ceilf((a - flo) / fdx);
        int jb = (int)ceilf((c - flo) / fdx);
        ja = min(max(ja, 0), NINT);
        jb = min(max(jb, 0), NINT);
        cnt += jb - ja;
    }

    // ---- warp reduce cnt + wsum, fold to per-block, publish ---------------
    cnt = __reduce_add_sync(FULLM, cnt);
    #pragma unroll
    for (int o = 16; o > 0; o >>= 1)
        wsum += __shfl_xor_sync(FULLM, wsum, o);
    if (lane == 0) { wci[wid] = cnt; wws[wid] = wsum; }
    __syncthreads();
    if (tid == 0) {
        int   c = 0; float w = 0.0f;
        #pragma unroll
        for (int i = 0; i < NWARP; ++i) { c += wci[i]; w += wws[i]; }
        g_cnt[b] = c;
        g_ws[b]  = w;
        __threadfence();
        unsigned t = atomicAdd(&g_bar2, 1u);
        bc_last = ((t % (unsigned)GBLK) == (unsigned)(GBLK - 1));
    }
    __syncthreads();

    // ---- last block to arrive performs the final fold ---------------------
    if (bc_last && wid == 0) {
        __threadfence();   // acquire: make all blocks' publishes visible
        int   c = g_cnt[lane] + g_cnt[lane + 32];
        float w = g_ws[lane]  + g_ws[lane + 32];
        c = __reduce_add_sync(FULLM, c);
        #pragma unroll
        for (int o = 16; o > 0; o >>= 1)
            w += __shfl_xor_sync(FULLM, w, o);
        if (lane == 0) {
            const float wmse = w / (float)NPIX;
            const float crps = (float)((double)c * (double)fdx / (double)NPIX);
            out[0] = 1e-4f * wmse + crps;
        }
    }
}

extern "C" void kernel_launch(void* const* d_in, const int* in_sizes, int n_in,
                              void* d_out, int out_size) {
    (void)in_sizes; (void)n_in; (void)out_size;
    const float* pred = (const float*)d_in[0];
    const float* tgt  = (const float*)d_in[1];
    float* out = (float*)d_out;

    fused_loss<<<GBLK, THREADS>>>(pred, tgt, out);
}

// round 5
// speedup vs baseline: 1.0025x; 1.0025x over previous
#include <cuda_runtime.h>
#include <math.h>

#define IMG_H   128
#define IMG_W   128
#define NB      4
#define IMG     (IMG_H * IMG_W)          // 16384
#define NPIX    (NB * IMG)               // 65536
#define NINT    1000
#define STRIPS  16
#define SROWS   8                        // output rows per strip
#define GBLK    (NB * STRIPS)            // 64 blocks (4 img x 16 strips)
#define THREADS 256
#define NWARP   (THREADS / 32)
#define ST      129                      // padded smem row stride
#define MAXR    16                       // 8 + 4 halo each side
#define FULLM   0xffffffffu
#define SLOT    32                       // u32 stride between seq slots (128B)

// Static device scratch (no allocations allowed).
// Sequence slots: block b owns g_seqX[b*SLOT]; incremented once per launch by
// that block only -> monotonic, replay-safe, no reset, no atomics.
__device__ volatile unsigned g_seq1[GBLK * SLOT];
__device__ volatile unsigned g_seq2[GBLK * SLOT];
__device__ float2 g_mnmx[GBLK];          // packed {min, max} per block
__device__ float2 g_cw[GBLK];            // packed {bits(cnt), wsum} per block

__global__ void __launch_bounds__(THREADS, 1)
fused_loss(const float* __restrict__ pred, const float* __restrict__ tgt,
           float* __restrict__ out) {
    __shared__ float imgA[MAXR * ST];    // pred strip
    __shared__ float imgB[MAXR * ST];    // tgt strip
    __shared__ float hsA [MAXR * ST];    // horizontal sums, pred
    __shared__ float hsB [MAXR * ST];    // horizontal sums, tgt
    __shared__ float wmn[NWARP], wmx[NWARP], wws[NWARP];
    __shared__ int   wci[NWARP];
    __shared__ float bc_lo, bc_dx;

    const int tid  = threadIdx.x;
    const int lane = tid & 31;
    const int wid  = tid >> 5;
    const int b    = blockIdx.x;
    const int im   = b >> 4;
    const int strip = b & 15;

    // per-launch sequence number (own slot, previous launch's value + 1)
    const unsigned sq = g_seq1[b * SLOT] + 1u;

    const int y0 = strip * SROWS;
    const int lo = max(0, y0 - 4);
    const int hi = min(IMG_H, y0 + SROWS + 4);
    const int nrows = hi - lo;

    // ---- load both strips (float4), fuse wmse on strip-owned rows --------
    float wsum = 0.0f;
    {
        const float4* p4 = (const float4*)(pred + (im * IMG + lo * IMG_W));
        const float4* t4 = (const float4*)(tgt  + (im * IMG + lo * IMG_W));
        const int n4 = nrows * (IMG_W / 4);
        for (int i = tid; i < n4; i += THREADS) {
            float4 pv = p4[i];
            float4 tv = t4[i];
            int base = i * 4;
            int r = base >> 7, x = base & 127;
            float* pa = imgA + r * ST + x;
            float* pb = imgB + r * ST + x;
            pa[0] = pv.x; pa[1] = pv.y; pa[2] = pv.z; pa[3] = pv.w;
            pb[0] = tv.x; pb[1] = tv.y; pb[2] = tv.z; pb[3] = tv.w;
            const int gy = lo + r;
            if (gy >= y0 && gy < y0 + SROWS) {
                float pp[4] = {pv.x, pv.y, pv.z, pv.w};
                float tt[4] = {tv.x, tv.y, tv.z, tv.w};
                #pragma unroll
                for (int k = 0; k < 4; ++k) {
                    float t = tt[k];
                    float w = 1.0f;
                    if (t >= 0.5f)  w = 2.0f;
                    if (t >= 2.0f)  w = 5.0f;
                    if (t >= 5.0f)  w = 10.0f;
                    if (t >= 10.0f) w = 30.0f;
                    float d = pp[k] - t;
                    wsum += w * d * d;
                }
            }
        }
    }
    // wmse warp reduction now (off critical path; visible after next sync)
    #pragma unroll
    for (int o = 16; o > 0; o >>= 1)
        wsum += __shfl_xor_sync(FULLM, wsum, o);
    if (lane == 0) wws[wid] = wsum;
    __syncthreads();

    // ---- horizontal sliding sums, BOTH tensors interleaved (ILP) ---------
    if (tid < nrows * 16) {
        const int r  = tid >> 4;
        const int x0 = (tid & 15) * 8;
        const float* rowA = imgA + r * ST;
        const float* rowB = imgB + r * ST;
        float* hrA = hsA + r * ST;
        float* hrB = hsB + r * ST;
        float sA = 0.0f, sB = 0.0f;
        #pragma unroll
        for (int dx = -4; dx <= 4; ++dx) {
            int xx = x0 + dx;
            if (xx >= 0 && xx < IMG_W) { sA += rowA[xx]; sB += rowB[xx]; }
        }
        #pragma unroll
        for (int k = 0; k < 8; ++k) {
            const int xc = x0 + k;
            hrA[xc] = sA; hrB[xc] = sB;
            if (xc + 5 < IMG_W) { sA += rowA[xc + 5]; sB += rowB[xc + 5]; }
            if (xc - 4 >= 0)    { sA -= rowA[xc - 4]; sB -= rowB[xc - 4]; }
        }
    }
    __syncthreads();

    // ---- vertical sliding sums + distance (regs), both tensors ----------
    const int x   = tid & 127;
    const int seg = tid >> 7;            // 0 or 1
    const int yb  = y0 + seg * 4;
    const int cx  = min(x + 4, IMG_W - 1) - max(x - 4, 0) + 1;

    float dA[4], dB[4];
    float mn = INFINITY, mx = -INFINITY;
    {
        float sA = 0.0f, sB = 0.0f;
        const int wlo = max(0, yb - 4), whi = min(IMG_H - 1, yb + 4);
        for (int yy = wlo; yy <= whi; ++yy) {
            sA += hsA[(yy - lo) * ST + x];
            sB += hsB[(yy - lo) * ST + x];
        }
        #pragma unroll
        for (int k = 0; k < 4; ++k) {
            const int y  = yb + k;
            const int cy = min(y + 4, IMG_H - 1) - max(y - 4, 0) + 1;
            const float inv = 1.0f / (float)(cx * cy);
            const float da = imgA[(y - lo) * ST + x] - sA * inv;
            const float db = imgB[(y - lo) * ST + x] - sB * inv;
            dA[k] = da; dB[k] = db;
            mn = fminf(mn, fminf(da, db));
            mx = fmaxf(mx, fmaxf(da, db));
            if (k < 3) {
                if (y + 5 < IMG_H) { sA += hsA[(y + 5 - lo) * ST + x];
                                     sB += hsB[(y + 5 - lo) * ST + x]; }
                if (y - 4 >= 0)    { sA -= hsA[(y - 4 - lo) * ST + x];
                                     sB -= hsB[(y - 4 - lo) * ST + x]; }
            }
        }
    }

    // ---- warp-shuffle min/max reduction ----------------------------------
    #pragma unroll
    for (int o = 16; o > 0; o >>= 1) {
        mn = fminf(mn, __shfl_xor_sync(FULLM, mn, o));
        mx = fmaxf(mx, __shfl_xor_sync(FULLM, mx, o));
    }
    if (lane == 0) { wmn[wid] = mn; wmx[wid] = mx; }
    __syncthreads();

    // ---- warp 0: publish block min/max, atomic-free barrier, fold lo/dx --
    if (wid == 0) {
        float m1 = (lane < NWARP) ? wmn[lane] : INFINITY;
        float m2 = (lane < NWARP) ? wmx[lane] : -INFINITY;
        #pragma unroll
        for (int o = 4; o > 0; o >>= 1) {
            m1 = fminf(m1, __shfl_xor_sync(FULLM, m1, o));
            m2 = fmaxf(m2, __shfl_xor_sync(FULLM, m2, o));
        }
        if (lane == 0) {
            g_mnmx[b] = make_float2(m1, m2);   // 8B store
            __threadfence();
            g_seq1[b * SLOT] = sq;             // arrival flag (own slot)
        }
        // poll: 2 slots per lane, parallel L2 loads, no atomics
        unsigned s1, s2;
        do {
            s1 = g_seq1[lane * SLOT];
            s2 = g_seq1[(lane + 32) * SLOT];
        } while (!__all_sync(FULLM, (s1 >= sq) && (s2 >= sq)));
        __threadfence();
        // fold 64 {min,max} pairs: 2 per lane, L2 (.cg bypasses L1)
        float2 a1 = __ldcg(&g_mnmx[lane]);
        float2 a2 = __ldcg(&g_mnmx[lane + 32]);
        m1 = fminf(a1.x, a2.x);
        m2 = fmaxf(a1.y, a2.y);
        #pragma unroll
        for (int o = 16; o > 0; o >>= 1) {
            m1 = fminf(m1, __shfl_xor_sync(FULLM, m1, o));
            m2 = fmaxf(m2, __shfl_xor_sync(FULLM, m2, o));
        }
        if (lane == 0) { bc_lo = m1; bc_dx = (m2 - m1) / (float)(NINT - 1); }
    }
    __syncthreads();
    const float flo = bc_lo;
    const float fdx = bc_dx;

    // ---- CRPS counts from register-resident dist pairs (exact ints) ------
    // count = #{ j in [0,NINT) : x_j in [min(dA,dB), max(dA,dB)) }, x_j=lo+j*dx
    int cnt = 0;
    #pragma unroll
    for (int k = 0; k < 4; ++k) {
        const float a = fminf(dA[k], dB[k]);
        const float c = fmaxf(dA[k], dB[k]);
        int ja = (int)ceilf((a - flo) / fdx);
        int jb = (int)ceilf((c - flo) / fdx);
        ja = min(max(ja, 0), NINT);
        jb = min(max(jb, 0), NINT);
        cnt += jb - ja;
    }
    cnt = __reduce_add_sync(FULLM, cnt);
    if (lane == 0) wci[wid] = cnt;
    __syncthreads();

    // ---- warp 0: publish {cnt, wsum}; only block 0 folds the final -------
    if (wid == 0) {
        if (lane == 0) {
            int   c = 0; float w = 0.0f;
            #pragma unroll
            for (int i = 0; i < NWARP; ++i) { c += wci[i]; w += wws[i]; }
            g_cw[b] = make_float2(__int_as_float(c), w);
            __threadfence();
            g_seq2[b * SLOT] = sq;             // publish flag
        }
        if (b == 0) {
            unsigned s1, s2;
            do {
                s1 = g_seq2[lane * SLOT];
                s2 = g_seq2[(lane + 32) * SLOT];
            } while (!__all_sync(FULLM, (s1 >= sq) && (s2 >= sq)));
            __threadfence();
            float2 a1 = __ldcg(&g_cw[lane]);
            float2 a2 = __ldcg(&g_cw[lane + 32]);
            int   c = __float_as_int(a1.x) + __float_as_int(a2.x);
            float w = a1.y + a2.y;
            c = __reduce_add_sync(FULLM, c);
            #pragma unroll
            for (int o = 16; o > 0; o >>= 1)
                w += __shfl_xor_sync(FULLM, w, o);
            if (lane == 0) {
                const float wmse = w / (float)NPIX;
                const float crps = (float)((double)c * (double)fdx / (double)NPIX);
                out[0] = 1e-4f * wmse + crps;
            }
        }
    }
}

extern "C" void kernel_launch(void* const* d_in, const int* in_sizes, int n_in,
                              void* d_out, int out_size) {
    (void)in_sizes; (void)n_in; (void)out_size;
    const float* pred = (const float*)d_in[0];
    const float* tgt  = (const float*)d_in[1];
    float* out = (float*)d_out;

    fused_loss<<<GBLK, THREADS>>>(pred, tgt, out);
}

// round 6
// speedup vs baseline: 1.1970x; 1.1940x over previous
#include <cuda_runtime.h>
#include <math.h>

#define IMG_H   128
#define IMG_W   128
#define NB      4
#define IMG     (IMG_H * IMG_W)          // 16384
#define NPIX    (NB * IMG)               // 65536
#define NINT    1000
#define STRIPS  16
#define SROWS   8                        // output rows per strip
#define GBLK    (NB * STRIPS)            // 64 blocks (4 img x 16 strips)
#define THREADS 256
#define NWARP   (THREADS / 32)
#define ST      129                      // padded smem row stride
#define MAXR    16                       // 8 + 4 halo each side
#define FULLM   0xffffffffu

// One 16B publish line per block, on its own 128B line (stride 8 Pubs).
// x = seq (monotonic per launch, replay-safe, never reset), y/z = payload.
struct alignas(16) Pub { unsigned x, y, z, w; };
__device__ Pub g_pub1[GBLK * 8];         // {seq, mapped_min, mapped_max}
__device__ Pub g_pub2[GBLK * 8];         // {seq, cnt, bits(wsum)}

// Single-transaction publish/observe (16B = one 32B sector -> sector-atomic).
__device__ __forceinline__ void st_rel_v4(Pub* p, unsigned a, unsigned b,
                                          unsigned c, unsigned d) {
    asm volatile("st.release.gpu.global.v4.b32 [%0], {%1,%2,%3,%4};"
                 :: "l"(p), "r"(a), "r"(b), "r"(c), "r"(d) : "memory");
}
__device__ __forceinline__ uint4 ld_acq_v4(const Pub* p) {
    uint4 v;
    asm volatile("ld.acquire.gpu.global.v4.b32 {%0,%1,%2,%3}, [%4];"
                 : "=r"(v.x), "=r"(v.y), "=r"(v.z), "=r"(v.w)
                 : "l"(p) : "memory");
    return v;
}
__device__ __forceinline__ unsigned ld_rlx(const unsigned* p) {
    unsigned v;
    asm volatile("ld.relaxed.gpu.global.b32 %0, [%1];" : "=r"(v) : "l"(p) : "memory");
    return v;
}

// Order-preserving float <-> uint map (no NaNs here).
__device__ __forceinline__ unsigned fmap(float f) {
    unsigned b = __float_as_uint(f);
    return (b & 0x80000000u) ? ~b : (b | 0x80000000u);
}
__device__ __forceinline__ float funmap(unsigned u) {
    return __uint_as_float((u & 0x80000000u) ? (u ^ 0x80000000u) : ~u);
}

__global__ void __launch_bounds__(THREADS, 1)
fused_loss(const float* __restrict__ pred, const float* __restrict__ tgt,
           float* __restrict__ out) {
    __shared__ float imgA[MAXR * ST];
    __shared__ float imgB[MAXR * ST];
    __shared__ float hsA [MAXR * ST];
    __shared__ float hsB [MAXR * ST];
    __shared__ unsigned wmn[NWARP], wmx[NWARP];
    __shared__ float wws[NWARP];
    __shared__ int   wci[NWARP];
    __shared__ float bc_lo, bc_rdx;

    const int tid  = threadIdx.x;
    const int lane = tid & 31;
    const int wid  = tid >> 5;
    const int b    = blockIdx.x;
    const int im   = b >> 4;
    const int strip = b & 15;

    // per-launch sequence number (own slot's previous value + 1)
    const unsigned sq = ld_rlx(&g_pub1[b * 8].x) + 1u;

    const int y0 = strip * SROWS;
    const int lo = max(0, y0 - 4);
    const int hi = min(IMG_H, y0 + SROWS + 4);
    const int nrows = hi - lo;

    // ---- load both strips (float4), fuse wmse on strip-owned rows --------
    float wsum = 0.0f;
    {
        const float4* p4 = (const float4*)(pred + (im * IMG + lo * IMG_W));
        const float4* t4 = (const float4*)(tgt  + (im * IMG + lo * IMG_W));
        const int n4 = nrows * (IMG_W / 4);
        for (int i = tid; i < n4; i += THREADS) {
            float4 pv = p4[i];
            float4 tv = t4[i];
            int base = i * 4;
            int r = base >> 7, x = base & 127;
            float* pa = imgA + r * ST + x;
            float* pb = imgB + r * ST + x;
            pa[0] = pv.x; pa[1] = pv.y; pa[2] = pv.z; pa[3] = pv.w;
            pb[0] = tv.x; pb[1] = tv.y; pb[2] = tv.z; pb[3] = tv.w;
            const int gy = lo + r;
            if (gy >= y0 && gy < y0 + SROWS) {
                float pp[4] = {pv.x, pv.y, pv.z, pv.w};
                float tt[4] = {tv.x, tv.y, tv.z, tv.w};
                #pragma unroll
                for (int k = 0; k < 4; ++k) {
                    float t = tt[k];
                    float w = 1.0f;
                    if (t >= 0.5f)  w = 2.0f;
                    if (t >= 2.0f)  w = 5.0f;
                    if (t >= 5.0f)  w = 10.0f;
                    if (t >= 10.0f) w = 30.0f;
                    float d = pp[k] - t;
                    wsum += w * d * d;
                }
            }
        }
    }
    // wmse warp reduction (off critical path)
    #pragma unroll
    for (int o = 16; o > 0; o >>= 1)
        wsum += __shfl_xor_sync(FULLM, wsum, o);
    if (lane == 0) wws[wid] = wsum;
    __syncthreads();

    // ---- horizontal sliding sums, both tensors interleaved ---------------
    if (tid < nrows * 16) {
        const int r  = tid >> 4;
        const int x0 = (tid & 15) * 8;
        const float* rowA = imgA + r * ST;
        const float* rowB = imgB + r * ST;
        float* hrA = hsA + r * ST;
        float* hrB = hsB + r * ST;
        float sA = 0.0f, sB = 0.0f;
        #pragma unroll
        for (int dx = -4; dx <= 4; ++dx) {
            int xx = x0 + dx;
            if (xx >= 0 && xx < IMG_W) { sA += rowA[xx]; sB += rowB[xx]; }
        }
        #pragma unroll
        for (int k = 0; k < 8; ++k) {
            const int xc = x0 + k;
            hrA[xc] = sA; hrB[xc] = sB;
            if (xc + 5 < IMG_W) { sA += rowA[xc + 5]; sB += rowB[xc + 5]; }
            if (xc - 4 >= 0)    { sA -= rowA[xc - 4]; sB -= rowB[xc - 4]; }
        }
    }
    __syncthreads();

    // ---- vertical sliding sums + distance (regs), both tensors ----------
    const int x   = tid & 127;
    const int seg = tid >> 7;
    const int yb  = y0 + seg * 4;
    const int cx  = min(x + 4, IMG_W - 1) - max(x - 4, 0) + 1;

    float dA[4], dB[4];
    float mn = INFINITY, mx = -INFINITY;
    {
        float sA = 0.0f, sB = 0.0f;
        const int wlo = max(0, yb - 4), whi = min(IMG_H - 1, yb + 4);
        for (int yy = wlo; yy <= whi; ++yy) {
            sA += hsA[(yy - lo) * ST + x];
            sB += hsB[(yy - lo) * ST + x];
        }
        #pragma unroll
        for (int k = 0; k < 4; ++k) {
            const int y  = yb + k;
            const int cy = min(y + 4, IMG_H - 1) - max(y - 4, 0) + 1;
            const float inv = 1.0f / (float)(cx * cy);
            const float da = imgA[(y - lo) * ST + x] - sA * inv;
            const float db = imgB[(y - lo) * ST + x] - sB * inv;
            dA[k] = da; dB[k] = db;
            mn = fminf(mn, fminf(da, db));
            mx = fmaxf(mx, fmaxf(da, db));
            if (k < 3) {
                if (y + 5 < IMG_H) { sA += hsA[(y + 5 - lo) * ST + x];
                                     sB += hsB[(y + 5 - lo) * ST + x]; }
                if (y - 4 >= 0)    { sA -= hsA[(y - 4 - lo) * ST + x];
                                     sB -= hsB[(y - 4 - lo) * ST + x]; }
            }
        }
    }

    // ---- REDUX min/max on order-mapped uints ------------------------------
    {
        unsigned umn = __reduce_min_sync(FULLM, fmap(mn));
        unsigned umx = __reduce_max_sync(FULLM, fmap(mx));
        if (lane == 0) { wmn[wid] = umn; wmx[wid] = umx; }
    }
    __syncthreads();

    // ---- warp 0: publish {seq,min,max} in ONE 16B release store; poll -----
    if (wid == 0) {
        unsigned m1 = (lane < NWARP) ? wmn[lane] : 0xFFFFFFFFu;
        unsigned m2 = (lane < NWARP) ? wmx[lane] : 0u;
        m1 = __reduce_min_sync(FULLM, m1);
        m2 = __reduce_max_sync(FULLM, m2);
        if (lane == 0) st_rel_v4(&g_pub1[b * 8], sq, m1, m2, 0u);

        uint4 v1, v2;
        do {
            v1 = ld_acq_v4(&g_pub1[lane * 8]);
            v2 = ld_acq_v4(&g_pub1[(lane + 32) * 8]);
        } while (!__all_sync(FULLM, (v1.x >= sq) && (v2.x >= sq)));

        unsigned mm1 = __reduce_min_sync(FULLM, min(v1.y, v2.y));
        unsigned mm2 = __reduce_max_sync(FULLM, max(v1.z, v2.z));
        if (lane == 0) {
            const float flo_ = funmap(mm1);
            const float fhi_ = funmap(mm2);
            const float fdx_ = (fhi_ - flo_) / (float)(NINT - 1);
            bc_lo  = flo_;
            bc_rdx = 1.0f / fdx_;
        }
    }
    __syncthreads();
    const float flo  = bc_lo;
    const float frdx = bc_rdx;

    // ---- CRPS counts from register-resident dist pairs (exact ints) ------
    // count = #{ j in [0,NINT) : x_j in [min(dA,dB), max(dA,dB)) }
    int cnt = 0;
    #pragma unroll
    for (int k = 0; k < 4; ++k) {
        const float a = fminf(dA[k], dB[k]);
        const float c = fmaxf(dA[k], dB[k]);
        int ja = (int)ceilf((a - flo) * frdx);
        int jb = (int)ceilf((c - flo) * frdx);
        ja = min(max(ja, 0), NINT);
        jb = min(max(jb, 0), NINT);
        cnt += jb - ja;
    }
    cnt = __reduce_add_sync(FULLM, cnt);
    if (lane == 0) wci[wid] = cnt;
    __syncthreads();

    // ---- publish {seq,cnt,wsum} in one 16B store; block 0 folds final ----
    if (wid == 0 && lane == 0) {
        int   c = 0; float w = 0.0f;
        #pragma unroll
        for (int i = 0; i < NWARP; ++i) { c += wci[i]; w += wws[i]; }
        st_rel_v4(&g_pub2[b * 8], sq, (unsigned)c, __float_as_uint(w), 0u);
    }
    if (b == 0 && wid == 0) {
        uint4 v1, v2;
        do {
            v1 = ld_acq_v4(&g_pub2[lane * 8]);
            v2 = ld_acq_v4(&g_pub2[(lane + 32) * 8]);
        } while (!__all_sync(FULLM, (v1.x >= sq) && (v2.x >= sq)));

        int   c = (int)v1.y + (int)v2.y;
        float w = __uint_as_float(v1.z) + __uint_as_float(v2.z);
        c = __reduce_add_sync(FULLM, c);
        #pragma unroll
        for (int o = 16; o > 0; o >>= 1)
            w += __shfl_xor_sync(FULLM, w, o);
        if (lane == 0) {
            // recover fdx from lo/rdx-free path: recompute from broadcast
            const float fdx_ = 1.0f / frdx;
            const float wmse = w / (float)NPIX;
            const float crps = (float)((double)c * (double)fdx_ / (double)NPIX);
            out[0] = 1e-4f * wmse + crps;
        }
    }
}

extern "C" void kernel_launch(void* const* d_in, const int* in_sizes, int n_in,
                              void* d_out, int out_size) {
    (void)in_sizes; (void)n_in; (void)out_size;
    const float* pred = (const float*)d_in[0];
    const float* tgt  = (const float*)d_in[1];
    float* out = (float*)d_out;

    fused_loss<<<GBLK, THREADS>>>(pred, tgt, out);
}